// round 4
// baseline (speedup 1.0000x reference)
#include <cuda_runtime.h>
#include <cuda_bf16.h>
#include <math.h>

#define BB 64
#define HH 512
#define AA 256
#define VV 10000
#define TT 151
#define LL 49
#define G3 1536

// ------------------------- device scratch (static, no allocs) -------------------------
__device__ float g_enc [BB*LL*HH];       // [b][l][d]
__device__ float g_att1[BB*LL*AA];       // [b][l][a]
__device__ float g_h   [BB*HH];
__device__ float g_inp [BB*HH];
__device__ float g_ctx [BB*HH];
__device__ float g_comb[BB*HH];
__device__ float g_comb_part[8][BB*HH];
__device__ float g_gi_part [4][BB*G3];
__device__ float g_gh_part [4][BB*G3];
__device__ float g_seq [BB*TT*HH];       // [b][t][d]

// ------------------------- P0: inp0 = embed[start], seq[:,0,:] -------------------------
__global__ void k_p0(const float* __restrict__ embed, const int* __restrict__ start){
    int b = blockIdx.x;
    int st = start ? start[0] : 1;
    for (int d = threadIdx.x; d < HH; d += blockDim.x){
        float v = embed[(size_t)st*HH + d];
        g_inp[b*HH + d] = v;
        g_seq[((size_t)b*TT + 0)*HH + d] = v;
    }
}

// ------------------------- P1: enc = X^T @ W_fp + b_fp ; h0 = mean_l enc -------------------------
// X = enc_feat [b][c][l]. grid (2 d-halves, 64 b), 256 thr; each thread one d, 49 l-accumulators.
__global__ void k_p1(const float* __restrict__ X, const float* __restrict__ Wfp,
                     const float* __restrict__ bfp){
    int b = blockIdx.y;
    int d = blockIdx.x*256 + threadIdx.x;
    __shared__ float Xs[16][LL];
    float acc[LL];
    #pragma unroll
    for (int l = 0; l < LL; l++) acc[l] = 0.f;
    for (int c0 = 0; c0 < HH; c0 += 16){
        __syncthreads();
        for (int idx = threadIdx.x; idx < 16*LL; idx += 256){
            int cl = idx / LL, l = idx - cl*LL;
            Xs[cl][l] = X[((size_t)b*HH + c0 + cl)*LL + l];
        }
        __syncthreads();
        #pragma unroll 1
        for (int cc = 0; cc < 16; cc++){
            float w = Wfp[(size_t)(c0+cc)*HH + d];
            #pragma unroll
            for (int l = 0; l < LL; l++) acc[l] = fmaf(Xs[cc][l], w, acc[l]);
        }
    }
    float bv = bfp[d];
    float s = 0.f;
    #pragma unroll
    for (int l = 0; l < LL; l++){
        g_enc[((size_t)b*LL + l)*HH + d] = acc[l] + bv;
        s += acc[l];
    }
    g_h[b*HH + d] = s*(1.f/(float)LL) + bv;
}

// ------------------------- P2: att1 = enc @ W_enc + b_enc -------------------------
__global__ void k_p2(const float* __restrict__ Wenc, const float* __restrict__ benc){
    int b = blockIdx.x, a = threadIdx.x;
    __shared__ float Es[16][LL];
    float acc[LL];
    #pragma unroll
    for (int l = 0; l < LL; l++) acc[l] = 0.f;
    for (int d0 = 0; d0 < HH; d0 += 16){
        __syncthreads();
        for (int idx = threadIdx.x; idx < 16*LL; idx += 256){
            int l = idx >> 4, dd = idx & 15;
            Es[dd][l] = g_enc[((size_t)b*LL + l)*HH + d0 + dd];
        }
        __syncthreads();
        #pragma unroll 1
        for (int dd = 0; dd < 16; dd++){
            float w = Wenc[(size_t)(d0+dd)*AA + a];
            #pragma unroll
            for (int l = 0; l < LL; l++) acc[l] = fmaf(Es[dd][l], w, acc[l]);
        }
    }
    float bv = benc[a];
    #pragma unroll
    for (int l = 0; l < LL; l++)
        g_att1[((size_t)b*LL + l)*AA + a] = acc[l] + bv;
}

// ------------------------- S1: att2 -> e -> softmax -> context (4 batches / CTA) -------------------------
__global__ void k_s1(const float* __restrict__ Wdec, const float* __restrict__ bdec,
                     const float* __restrict__ Wfull, const float* __restrict__ bfull){
    __shared__ float hs[4][HH];
    __shared__ float att2s[4][AA];
    __shared__ float es[4][64];
    __shared__ float alphas[4][64];
    int b0 = blockIdx.x*4;
    int tid = threadIdx.x;

    #pragma unroll
    for (int i = 0; i < 8; i++){
        int idx = tid + i*256;            // 2048 = 4*512
        int bi = idx >> 9, d = idx & 511;
        hs[bi][d] = g_h[(b0+bi)*HH + d];
    }
    __syncthreads();

    // att2[bi][a] = h[bi] . W_dec[:,a] + b_dec[a]
    {
        int a = tid;                      // 0..255
        float a0=0.f, a1=0.f, a2=0.f, a3=0.f;
        for (int d = 0; d < HH; d++){
            float w = Wdec[d*AA + a];
            a0 = fmaf(hs[0][d], w, a0);
            a1 = fmaf(hs[1][d], w, a1);
            a2 = fmaf(hs[2][d], w, a2);
            a3 = fmaf(hs[3][d], w, a3);
        }
        float bd = bdec[a];
        att2s[0][a]=a0+bd; att2s[1][a]=a1+bd; att2s[2][a]=a2+bd; att2s[3][a]=a3+bd;
    }
    __syncthreads();

    // e[bi][l] = tanh(att1 + att2) . W_full + b_full
    int warp = tid >> 5, lane = tid & 31;
    for (int task = warp; task < 4*LL; task += 8){
        int bi = task / LL, l = task - bi*LL;
        const float* a1p = g_att1 + ((size_t)(b0+bi)*LL + l)*AA;
        float s = 0.f;
        #pragma unroll
        for (int k = 0; k < 8; k++){
            int a = lane + k*32;
            s = fmaf(tanhf(a1p[a] + att2s[bi][a]), Wfull[a], s);
        }
        #pragma unroll
        for (int o = 16; o > 0; o >>= 1) s += __shfl_xor_sync(0xffffffffu, s, o);
        if (lane == 0) es[bi][l] = s + bfull[0];
    }
    __syncthreads();

    // softmax over l (one warp per batch)
    if (warp < 4){
        int bi = warp;
        int l1 = lane, l2 = lane + 32;
        float e1 = (l1 < LL) ? es[bi][l1] : -1e30f;
        float e2 = (l2 < LL) ? es[bi][l2] : -1e30f;
        float m = fmaxf(e1, e2);
        #pragma unroll
        for (int o = 16; o > 0; o >>= 1) m = fmaxf(m, __shfl_xor_sync(0xffffffffu, m, o));
        float p1 = (l1 < LL) ? expf(e1 - m) : 0.f;
        float p2 = (l2 < LL) ? expf(e2 - m) : 0.f;
        float s = p1 + p2;
        #pragma unroll
        for (int o = 16; o > 0; o >>= 1) s += __shfl_xor_sync(0xffffffffu, s, o);
        float inv = 1.f/s;
        if (l1 < LL) alphas[bi][l1] = p1*inv;
        if (l2 < LL) alphas[bi][l2] = p2*inv;
    }
    __syncthreads();

    // context[bi][d] = sum_l alpha * enc
    {
        int d0 = tid, d1 = tid + 256;
        #pragma unroll
        for (int bi = 0; bi < 4; bi++){
            const float* eb = g_enc + (size_t)(b0+bi)*LL*HH;
            float c0 = 0.f, c1 = 0.f;
            #pragma unroll 7
            for (int l = 0; l < LL; l++){
                float al = alphas[bi][l];
                c0 = fmaf(al, eb[l*HH + d0], c0);
                c1 = fmaf(al, eb[l*HH + d1], c1);
            }
            g_ctx[(b0+bi)*HH + d0] = c0;
            g_ctx[(b0+bi)*HH + d1] = c1;
        }
    }
}

// ------------------------- S2: comb partials. cat=[inp|ctx] @ W_comb. grid(8 n-tiles, 8 k-splits) -------------------------
__global__ void k_s2(const float* __restrict__ Wcomb){
    __shared__ float As[64][33];
    __shared__ float Ws[32][65];
    int n0 = blockIdx.x*64, k0 = blockIdx.y*128;
    int tid = threadIdx.x, tx = tid & 15, ty = tid >> 4;
    float acc[4][4];
    #pragma unroll
    for (int i=0;i<4;i++)
        #pragma unroll
        for (int j=0;j<4;j++) acc[i][j]=0.f;

    for (int ks = 0; ks < 4; ks++){
        int kb = k0 + ks*32;
        __syncthreads();
        #pragma unroll
        for (int i = 0; i < 8; i++){
            int idx = tid + i*256;        // 2048 = 64*32
            int b = idx >> 5, kk = idx & 31;
            int k = kb + kk;
            As[b][kk] = (k < HH) ? g_inp[b*HH + k] : g_ctx[b*HH + (k - HH)];
        }
        #pragma unroll
        for (int i = 0; i < 8; i++){
            int idx = tid + i*256;        // 2048 = 32*64
            int n = idx & 63, kk = idx >> 6;
            Ws[kk][n] = Wcomb[(size_t)(kb + kk)*HH + n0 + n];
        }
        __syncthreads();
        #pragma unroll 8
        for (int kk = 0; kk < 32; kk++){
            float a[4], w[4];
            #pragma unroll
            for (int i = 0; i < 4; i++) a[i] = As[ty*4+i][kk];
            #pragma unroll
            for (int j = 0; j < 4; j++) w[j] = Ws[kk][tx*4+j];
            #pragma unroll
            for (int i = 0; i < 4; i++)
                #pragma unroll
                for (int j = 0; j < 4; j++)
                    acc[i][j] = fmaf(a[i], w[j], acc[i][j]);
        }
    }
    float* outp = g_comb_part[blockIdx.y];
    #pragma unroll
    for (int i = 0; i < 4; i++)
        #pragma unroll
        for (int j = 0; j < 4; j++)
            outp[(ty*4+i)*HH + n0 + tx*4 + j] = acc[i][j];
}

// ------------------------- S3: comb = tanh(sum partials + b_comb) -------------------------
__global__ void k_s3(const float* __restrict__ bcomb){
    int i = blockIdx.x*256 + threadIdx.x;    // < 32768
    int n = i & 511;
    float s = bcomb[n];
    #pragma unroll
    for (int p = 0; p < 8; p++) s += g_comb_part[p][i];
    g_comb[i] = tanhf(s);
}

// ------------------------- S4: gi/gh partials. grid(24 j-tiles, 4 k-splits, 2 {gi,gh}) -------------------------
__global__ void k_s4(const float* __restrict__ Wih, const float* __restrict__ Whh){
    __shared__ float As[64][33];
    __shared__ float Ws[32][65];
    int j0 = blockIdx.x*64, k0 = blockIdx.y*128;
    const float* Aptr = (blockIdx.z == 0) ? g_comb : g_h;
    const float* W    = (blockIdx.z == 0) ? Wih : Whh;
    float* outp = (blockIdx.z == 0) ? g_gi_part[blockIdx.y] : g_gh_part[blockIdx.y];
    int tid = threadIdx.x, tx = tid & 15, ty = tid >> 4;
    float acc[4][4];
    #pragma unroll
    for (int i=0;i<4;i++)
        #pragma unroll
        for (int j=0;j<4;j++) acc[i][j]=0.f;

    for (int ks = 0; ks < 4; ks++){
        int kb = k0 + ks*32;
        __syncthreads();
        #pragma unroll
        for (int i = 0; i < 8; i++){
            int idx = tid + i*256;
            int b = idx >> 5, kk = idx & 31;
            As[b][kk] = Aptr[b*HH + kb + kk];
        }
        #pragma unroll
        for (int i = 0; i < 8; i++){
            int idx = tid + i*256;        // 2048 = 64 j * 32 k
            int kk = idx & 31, j = idx >> 5;
            Ws[kk][j] = W[(size_t)(j0 + j)*HH + kb + kk];
        }
        __syncthreads();
        #pragma unroll 8
        for (int kk = 0; kk < 32; kk++){
            float a[4], w[4];
            #pragma unroll
            for (int i = 0; i < 4; i++) a[i] = As[ty*4+i][kk];
            #pragma unroll
            for (int j = 0; j < 4; j++) w[j] = Ws[kk][tx*4+j];
            #pragma unroll
            for (int i = 0; i < 4; i++)
                #pragma unroll
                for (int j = 0; j < 4; j++)
                    acc[i][j] = fmaf(a[i], w[j], acc[i][j]);
        }
    }
    #pragma unroll
    for (int i = 0; i < 4; i++)
        #pragma unroll
        for (int j = 0; j < 4; j++)
            outp[(ty*4+i)*G3 + j0 + tx*4 + j] = acc[i][j];
}

// ------------------------- S5: GRU combine, write h_new / inp / seq[t] -------------------------
__global__ void k_s5(const float* __restrict__ bih, const float* __restrict__ bhh, int t){
    int i = blockIdx.x*256 + threadIdx.x;      // < 32768
    int b = i >> 9, j = i & 511;
    float gir = bih[j],       giz = bih[512+j],  gin = bih[1024+j];
    float ghr = bhh[j],       ghz = bhh[512+j],  ghn = bhh[1024+j];
    #pragma unroll
    for (int p = 0; p < 4; p++){
        const float* gi = g_gi_part[p] + (size_t)b*G3;
        const float* gh = g_gh_part[p] + (size_t)b*G3;
        gir += gi[j];      giz += gi[512+j];  gin += gi[1024+j];
        ghr += gh[j];      ghz += gh[512+j];  ghn += gh[1024+j];
    }
    float h = g_h[i];
    float r = 1.f/(1.f + expf(-(gir + ghr)));
    float z = 1.f/(1.f + expf(-(giz + ghz)));
    float n = tanhf(gin + r*ghn);
    float hn = (1.f - z)*n + z*h;
    g_h[i] = hn;
    g_inp[i] = hn;
    g_seq[((size_t)b*TT + t)*HH + j] = hn;
}

// ------------------------- Final: res = seq @ W_proj + b_proj, stored [B][V][T] -------------------------
__global__ void __launch_bounds__(256, 2)
k_sf(const float* __restrict__ Wp, const float* __restrict__ bp, float* __restrict__ out){
    __shared__ float sm[4224];            // As[16][132] | Bs[16][132] ; reused as sbuf[32][129]
    float* As = sm;
    float* Bs = sm + 2112;
    int m0 = blockIdx.x*128, n0 = blockIdx.y*128;
    int tid = threadIdx.x, tx = tid & 15, ty = tid >> 4;
    float acc[8][8];
    #pragma unroll
    for (int i=0;i<8;i++)
        #pragma unroll
        for (int j=0;j<8;j++) acc[i][j]=0.f;

    for (int kc = 0; kc < HH; kc += 16){
        __syncthreads();
        #pragma unroll
        for (int i = 0; i < 8; i++){
            int idx = tid + i*256;        // 2048 = 128 m * 16 k
            int kk = idx & 15, m = idx >> 4;
            int r = m0 + m;
            As[kk*132 + m] = (r < BB*TT) ? g_seq[(size_t)r*HH + kc + kk] : 0.f;
        }
        #pragma unroll
        for (int i = 0; i < 8; i++){
            int idx = tid + i*256;        // 2048 = 16 k * 128 n
            int n = idx & 127, kk = idx >> 7;
            int v = n0 + n;
            Bs[kk*132 + n] = (v < VV) ? Wp[(size_t)(kc+kk)*VV + v] : 0.f;
        }
        __syncthreads();
        #pragma unroll 4
        for (int kk = 0; kk < 16; kk++){
            float a[8], w[8];
            #pragma unroll
            for (int i = 0; i < 8; i++) a[i] = As[kk*132 + ty*8 + i];
            #pragma unroll
            for (int j = 0; j < 8; j++) w[j] = Bs[kk*132 + tx*8 + j];
            #pragma unroll
            for (int i = 0; i < 8; i++)
                #pragma unroll
                for (int j = 0; j < 8; j++)
                    acc[i][j] = fmaf(a[i], w[j], acc[i][j]);
        }
    }
    // bias
    #pragma unroll
    for (int j = 0; j < 8; j++){
        int v = n0 + tx*8 + j;
        float bj = (v < VV) ? bp[v] : 0.f;
        #pragma unroll
        for (int i = 0; i < 8; i++) acc[i][j] += bj;
    }
    // transposed store via smem (32 output columns per pass)
    float* sbuf = sm;                     // [32][129]
    int lane = tid & 31, cbase = tid >> 5;
    for (int cg = 0; cg < 4; cg++){
        __syncthreads();
        if ((tx >> 2) == cg){
            #pragma unroll
            for (int j = 0; j < 8; j++){
                int cl = (tx & 3)*8 + j;
                #pragma unroll
                for (int i = 0; i < 8; i++)
                    sbuf[cl*129 + ty*8 + i] = acc[i][j];
            }
        }
        __syncthreads();
        #pragma unroll
        for (int cc = 0; cc < 4; cc++){
            int cl = cbase + cc*8;        // 0..31
            int v = n0 + cg*32 + cl;
            if (v < VV){
                #pragma unroll
                for (int q = 0; q < 4; q++){
                    int m = lane + q*32;
                    int r = m0 + m;
                    if (r < BB*TT){
                        int b = r / TT;
                        int t = r - b*TT;
                        out[(size_t)b*VV*TT + (size_t)v*TT + t] = sbuf[cl*129 + m];
                    }
                }
            }
        }
    }
}

// ------------------------- Argmax over V (tokens), t-coalesced -------------------------
__global__ void k_ag(float* __restrict__ out, int write_tok){
    int b = blockIdx.x;
    int t = threadIdx.x;
    if (t >= TT) return;
    const float* base = out + (size_t)b*VV*TT + t;
    float best = base[0];
    int bi = 0;
    #pragma unroll 4
    for (int v = 1; v < VV; v++){
        float x = base[(size_t)v*TT];
        if (x > best){ best = x; bi = v; }
    }
    if (write_tok)
        out[(size_t)BB*VV*TT + (size_t)b*TT + t] = (float)bi;
}

// ------------------------- launch -------------------------
extern "C" void kernel_launch(void* const* d_in, const int* in_sizes, int n_in,
                              void* d_out, int out_size){
    const float* enc_feat = (const float*)d_in[0];
    const float* W_fp   = (const float*)d_in[1];
    const float* b_fp   = (const float*)d_in[2];
    const float* W_enc  = (const float*)d_in[3];
    const float* b_enc  = (const float*)d_in[4];
    const float* W_dec  = (const float*)d_in[5];
    const float* b_dec  = (const float*)d_in[6];
    const float* W_full = (const float*)d_in[7];
    const float* b_full = (const float*)d_in[8];
    const float* W_comb = (const float*)d_in[9];
    const float* b_comb = (const float*)d_in[10];
    const float* embed  = (const float*)d_in[11];
    const float* W_ih   = (const float*)d_in[12];
    const float* b_ih   = (const float*)d_in[13];
    const float* W_hh   = (const float*)d_in[14];
    const float* b_hh   = (const float*)d_in[15];
    const float* W_proj = (const float*)d_in[16];
    const float* b_proj = (const float*)d_in[17];
    const int* start    = (n_in >= 19) ? (const int*)d_in[18] : nullptr;
    float* out = (float*)d_out;

    k_p0<<<BB, 256>>>(embed, start);
    k_p1<<<dim3(2, BB), 256>>>(enc_feat, W_fp, b_fp);
    k_p2<<<BB, 256>>>(W_enc, b_enc);

    for (int t = 1; t < TT; t++){
        k_s1<<<16, 256>>>(W_dec, b_dec, W_full, b_full);
        k_s2<<<dim3(8, 8), 256>>>(W_comb);
        k_s3<<<128, 256>>>(b_comb);
        k_s4<<<dim3(24, 4, 2), 256>>>(W_ih, W_hh);
        k_s5<<<128, 256>>>(b_ih, b_hh, t);
    }

    k_sf<<<dim3(76, 79), 256>>>(W_proj, b_proj, out);

    int write_tok = (out_size >= BB*VV*TT + BB*TT) ? 1 : 0;
    k_ag<<<BB, 192>>>(out, write_tok);
}

// round 5
// speedup vs baseline: 1.7418x; 1.7418x over previous
#include <cuda_runtime.h>
#include <cuda_bf16.h>
#include <math.h>

#define BB 64
#define HH 512
#define AA 256
#define VV 10000
#define TT 151
#define LL 49
#define G3 1536
#define NBLK 128

typedef unsigned long long ull;

// ------------------------- device scratch (static, no allocs) -------------------------
__device__ float g_enc [BB*LL*HH];       // [b][l][d]
__device__ float g_att1[BB*LL*AA];       // [b][l][a]
__device__ float g_h   [BB*HH];
__device__ float g_inp [BB*HH];
__device__ float g_ctx [BB*HH];
__device__ float g_comb[BB*HH];
__device__ float g_att2p[8][BB*AA];      // att2 k-split partials
__device__ float g_combp[16][BB*HH];     // comb k-split partials
__device__ float g_ghp [4][BB*G3];       // gh partials
__device__ float g_gip [4][BB*G3];       // gi partials
__device__ float g_ghsum[BB*G3];         // reduced gh + b_hh
__device__ float g_seq [BB*TT*HH];       // [b][t][d]
__device__ unsigned g_cnt;
__device__ unsigned g_rel;

// ------------------------- grid barrier (monotonic ticket) -------------------------
__device__ __forceinline__ void gsync(){
    __syncthreads();
    if (threadIdx.x == 0){
        __threadfence();                                     // release: make my CTA's writes visible
        unsigned t = atomicAdd(&g_cnt, 1u) + 1u;
        unsigned target = ((t + NBLK - 1u)/NBLK)*NBLK;       // end of my generation
        if (t == target){
            atomicMax(&g_rel, target);
        } else {
            unsigned v;
            do { v = *(volatile unsigned*)&g_rel; } while (v < target);
        }
        __threadfence();                                     // acquire: invalidate L1 before reads
    }
    __syncthreads();
}

__global__ void k_rst(){ g_cnt = 0u; g_rel = 0u; }

// ------------------------- P0: inp0 = embed[start], seq[:,0,:] -------------------------
__global__ void k_p0(const float* __restrict__ embed, const int* __restrict__ start){
    int b = blockIdx.x;
    int st = start ? start[0] : 1;
    for (int d = threadIdx.x; d < HH; d += blockDim.x){
        float v = embed[(size_t)st*HH + d];
        g_inp[b*HH + d] = v;
        g_seq[((size_t)b*TT + 0)*HH + d] = v;
    }
}

// ------------------------- P1: enc = X^T @ W_fp + b_fp ; h0 = mean_l enc -------------------------
__global__ void k_p1(const float* __restrict__ X, const float* __restrict__ Wfp,
                     const float* __restrict__ bfp){
    int b = blockIdx.y;
    int d = blockIdx.x*256 + threadIdx.x;
    __shared__ float Xs[16][LL];
    float acc[LL];
    #pragma unroll
    for (int l = 0; l < LL; l++) acc[l] = 0.f;
    for (int c0 = 0; c0 < HH; c0 += 16){
        __syncthreads();
        for (int idx = threadIdx.x; idx < 16*LL; idx += 256){
            int cl = idx / LL, l = idx - cl*LL;
            Xs[cl][l] = X[((size_t)b*HH + c0 + cl)*LL + l];
        }
        __syncthreads();
        #pragma unroll 1
        for (int cc = 0; cc < 16; cc++){
            float w = Wfp[(size_t)(c0+cc)*HH + d];
            #pragma unroll
            for (int l = 0; l < LL; l++) acc[l] = fmaf(Xs[cc][l], w, acc[l]);
        }
    }
    float bv = bfp[d];
    float s = 0.f;
    #pragma unroll
    for (int l = 0; l < LL; l++){
        g_enc[((size_t)b*LL + l)*HH + d] = acc[l] + bv;
        s += acc[l];
    }
    g_h[b*HH + d] = s*(1.f/(float)LL) + bv;
}

// ------------------------- P2: att1 = enc @ W_enc + b_enc -------------------------
__global__ void k_p2(const float* __restrict__ Wenc, const float* __restrict__ benc){
    int b = blockIdx.x, a = threadIdx.x;
    __shared__ float Es[16][LL];
    float acc[LL];
    #pragma unroll
    for (int l = 0; l < LL; l++) acc[l] = 0.f;
    for (int d0 = 0; d0 < HH; d0 += 16){
        __syncthreads();
        for (int idx = threadIdx.x; idx < 16*LL; idx += 256){
            int l = idx >> 4, dd = idx & 15;
            Es[dd][l] = g_enc[((size_t)b*LL + l)*HH + d0 + dd];
        }
        __syncthreads();
        #pragma unroll 1
        for (int dd = 0; dd < 16; dd++){
            float w = Wenc[(size_t)(d0+dd)*AA + a];
            #pragma unroll
            for (int l = 0; l < LL; l++) acc[l] = fmaf(Es[dd][l], w, acc[l]);
        }
    }
    float bv = benc[a];
    #pragma unroll
    for (int l = 0; l < LL; l++)
        g_att1[((size_t)b*LL + l)*AA + a] = acc[l] + bv;
}

// ------------------------- 64x64 microtile accumulate over 32-k smem stage -------------------------
__device__ __forceinline__ void mt32(const float* __restrict__ As, const float* __restrict__ Ws,
                                     int tx, int ty, float acc[4][4]){
    #pragma unroll 8
    for (int kk = 0; kk < 32; kk++){
        float a[4], w[4];
        #pragma unroll
        for (int i = 0; i < 4; i++) a[i] = As[(ty*4+i)*33 + kk];
        #pragma unroll
        for (int j = 0; j < 4; j++) w[j] = Ws[kk*65 + tx*4 + j];
        #pragma unroll
        for (int i = 0; i < 4; i++)
            #pragma unroll
            for (int j = 0; j < 4; j++)
                acc[i][j] = fmaf(a[i], w[j], acc[i][j]);
    }
}

// ------------------------- persistent step kernel (all 150 steps) -------------------------
__global__ void __launch_bounds__(256)
k_step(const float* __restrict__ Wdec,  const float* __restrict__ bdec,
       const float* __restrict__ Wfull, const float* __restrict__ bfull,
       const float* __restrict__ Wcomb, const float* __restrict__ bcomb,
       const float* __restrict__ Wih,   const float* __restrict__ bih,
       const float* __restrict__ Whh,   const float* __restrict__ bhh)
{
    __shared__ __align__(16) float As[64*33];   // 2112 floats
    __shared__ __align__(16) float Ws[32*65];   // 2080 floats
    const int blk = blockIdx.x, tid = threadIdx.x;
    const int tx = tid & 15, ty = tid >> 4;
    const int warp = tid >> 5, lane = tid & 31;

    for (int t = 1; t < TT; t++){
        // ======== P1: att2 partials (blk<32) + gh partials (blk>=32) ========
        if (blk < 32){
            int at = blk & 3, ks = blk >> 2;
            int n0 = at*64, k0 = ks*64;
            float acc[4][4];
            #pragma unroll
            for (int i=0;i<4;i++)
                #pragma unroll
                for (int j=0;j<4;j++) acc[i][j]=0.f;
            for (int s = 0; s < 2; s++){
                int kb = k0 + s*32;
                __syncthreads();
                #pragma unroll
                for (int i = 0; i < 8; i++){
                    int idx = tid + i*256; int b = idx >> 5, kk = idx & 31;
                    As[b*33 + kk] = g_h[b*HH + kb + kk];
                }
                #pragma unroll
                for (int i = 0; i < 8; i++){
                    int idx = tid + i*256; int n = idx & 63, kk = idx >> 6;
                    Ws[kk*65 + n] = Wdec[(size_t)(kb+kk)*AA + n0 + n];
                }
                __syncthreads();
                mt32(As, Ws, tx, ty, acc);
            }
            float* outp = g_att2p[ks];
            #pragma unroll
            for (int i = 0; i < 4; i++)
                #pragma unroll
                for (int j = 0; j < 4; j++)
                    outp[(ty*4+i)*AA + n0 + tx*4 + j] = acc[i][j];
        } else {
            int rem = blk - 32;                  // 0..95
            int jt = rem % 24, ks = rem / 24;    // 24 j-tiles, 4 k-splits of 128
            int j0 = jt*64, k0 = ks*128;
            float acc[4][4];
            #pragma unroll
            for (int i=0;i<4;i++)
                #pragma unroll
                for (int j=0;j<4;j++) acc[i][j]=0.f;
            for (int s = 0; s < 4; s++){
                int kb = k0 + s*32;
                __syncthreads();
                #pragma unroll
                for (int i = 0; i < 8; i++){
                    int idx = tid + i*256; int b = idx >> 5, kk = idx & 31;
                    As[b*33 + kk] = g_h[b*HH + kb + kk];
                }
                #pragma unroll
                for (int i = 0; i < 8; i++){
                    int idx = tid + i*256; int kk = idx & 31, j = idx >> 5;
                    Ws[kk*65 + j] = Whh[(size_t)(j0+j)*HH + kb + kk];
                }
                __syncthreads();
                mt32(As, Ws, tx, ty, acc);
            }
            float* outp = g_ghp[ks];
            #pragma unroll
            for (int i = 0; i < 4; i++)
                #pragma unroll
                for (int j = 0; j < 4; j++)
                    outp[(ty*4+i)*G3 + j0 + tx*4 + j] = acc[i][j];
        }
        gsync();

        // ======== P2: per-batch attention (blk<64) | gh reduce (blk>=64) ========
        if (blk < 64){
            int b = blk;
            // att2 reduce into As[0..255]
            {
                int a = tid;
                float s = bdec[a];
                #pragma unroll
                for (int p = 0; p < 8; p++) s += g_att2p[p][b*AA + a];
                As[a] = s;
            }
            __syncthreads();
            // e[l] into As[256+l]
            for (int l = warp; l < LL; l += 8){
                const float* a1p = g_att1 + ((size_t)b*LL + l)*AA;
                float s = 0.f;
                #pragma unroll
                for (int k = 0; k < 8; k++){
                    int a = lane + k*32;
                    s = fmaf(tanhf(a1p[a] + As[a]), Wfull[a], s);
                }
                #pragma unroll
                for (int o = 16; o > 0; o >>= 1) s += __shfl_xor_sync(0xffffffffu, s, o);
                if (lane == 0) As[256 + l] = s + bfull[0];
            }
            __syncthreads();
            // softmax into As[320+l]
            if (warp == 0){
                int l1 = lane, l2 = lane + 32;
                float e1 = (l1 < LL) ? As[256+l1] : -1e30f;
                float e2 = (l2 < LL) ? As[256+l2] : -1e30f;
                float m = fmaxf(e1, e2);
                #pragma unroll
                for (int o = 16; o > 0; o >>= 1) m = fmaxf(m, __shfl_xor_sync(0xffffffffu, m, o));
                float p1 = (l1 < LL) ? expf(e1 - m) : 0.f;
                float p2 = (l2 < LL) ? expf(e2 - m) : 0.f;
                float sm = p1 + p2;
                #pragma unroll
                for (int o = 16; o > 0; o >>= 1) sm += __shfl_xor_sync(0xffffffffu, sm, o);
                float inv = 1.f/sm;
                if (l1 < LL) As[320 + l1] = p1*inv;
                if (l2 < LL) As[320 + l2] = p2*inv;
            }
            __syncthreads();
            // context
            {
                int d0 = tid, d1 = tid + 256;
                const float* eb = g_enc + (size_t)b*LL*HH;
                float c0 = 0.f, c1 = 0.f;
                #pragma unroll 7
                for (int l = 0; l < LL; l++){
                    float al = As[320 + l];
                    c0 = fmaf(al, eb[l*HH + d0], c0);
                    c1 = fmaf(al, eb[l*HH + d1], c1);
                }
                g_ctx[b*HH + d0] = c0;
                g_ctx[b*HH + d1] = c1;
            }
        } else {
            int b = blk - 64;
            for (int j = tid; j < G3; j += 256){
                float s = bhh[j];
                #pragma unroll
                for (int p = 0; p < 4; p++) s += g_ghp[p][b*G3 + j];
                g_ghsum[b*G3 + j] = s;
            }
        }
        gsync();

        // ======== P3: comb partials: [inp|ctx] @ W_comb ========
        {
            int nt = blk & 7, ks = blk >> 3;     // 8 n-tiles, 16 k-splits of 64
            int n0 = nt*64, k0 = ks*64;
            float acc[4][4];
            #pragma unroll
            for (int i=0;i<4;i++)
                #pragma unroll
                for (int j=0;j<4;j++) acc[i][j]=0.f;
            for (int s = 0; s < 2; s++){
                int kb = k0 + s*32;
                __syncthreads();
                #pragma unroll
                for (int i = 0; i < 8; i++){
                    int idx = tid + i*256; int b = idx >> 5, kk = idx & 31;
                    int k = kb + kk;
                    As[b*33 + kk] = (k < HH) ? g_inp[b*HH + k] : g_ctx[b*HH + (k - HH)];
                }
                #pragma unroll
                for (int i = 0; i < 8; i++){
                    int idx = tid + i*256; int n = idx & 63, kk = idx >> 6;
                    Ws[kk*65 + n] = Wcomb[(size_t)(kb+kk)*HH + n0 + n];
                }
                __syncthreads();
                mt32(As, Ws, tx, ty, acc);
            }
            float* outp = g_combp[ks];
            #pragma unroll
            for (int i = 0; i < 4; i++)
                #pragma unroll
                for (int j = 0; j < 4; j++)
                    outp[(ty*4+i)*HH + n0 + tx*4 + j] = acc[i][j];
        }
        gsync();

        // ======== P4: comb reduce + tanh ========
        {
            int i = blk*256 + tid;               // < 32768
            int n = i & 511;
            float s = bcomb[n];
            #pragma unroll
            for (int p = 0; p < 16; p++) s += g_combp[p][i];
            g_comb[i] = tanhf(s);
        }
        gsync();

        // ======== P5: gi partials: comb @ W_ih^T ========
        if (blk < 96){
            int jt = blk % 24, ks = blk / 24;    // 24 j-tiles, 4 k-splits of 128
            int j0 = jt*64, k0 = ks*128;
            float acc[4][4];
            #pragma unroll
            for (int i=0;i<4;i++)
                #pragma unroll
                for (int j=0;j<4;j++) acc[i][j]=0.f;
            for (int s = 0; s < 4; s++){
                int kb = k0 + s*32;
                __syncthreads();
                #pragma unroll
                for (int i = 0; i < 8; i++){
                    int idx = tid + i*256; int b = idx >> 5, kk = idx & 31;
                    As[b*33 + kk] = g_comb[b*HH + kb + kk];
                }
                #pragma unroll
                for (int i = 0; i < 8; i++){
                    int idx = tid + i*256; int kk = idx & 31, j = idx >> 5;
                    Ws[kk*65 + j] = Wih[(size_t)(j0+j)*HH + kb + kk];
                }
                __syncthreads();
                mt32(As, Ws, tx, ty, acc);
            }
            float* outp = g_gip[ks];
            #pragma unroll
            for (int i = 0; i < 4; i++)
                #pragma unroll
                for (int j = 0; j < 4; j++)
                    outp[(ty*4+i)*G3 + j0 + tx*4 + j] = acc[i][j];
        }
        gsync();

        // ======== P6: GRU pointwise -> h, inp, seq[t] ========
        {
            int i = blk*256 + tid;               // < 32768
            int b = i >> 9, j = i & 511;
            float gir = bih[j], giz = bih[512+j], gin = bih[1024+j];
            #pragma unroll
            for (int p = 0; p < 4; p++){
                const float* gi = g_gip[p] + (size_t)b*G3;
                gir += gi[j]; giz += gi[512+j]; gin += gi[1024+j];
            }
            const float* gh = g_ghsum + (size_t)b*G3;
            float ghr = gh[j], ghz = gh[512+j], ghn = gh[1024+j];
            float h = g_h[i];
            float r = 1.f/(1.f + expf(-(gir + ghr)));
            float z = 1.f/(1.f + expf(-(giz + ghz)));
            float n = tanhf(gin + r*ghn);
            float hn = (1.f - z)*n + z*h;
            g_h[i] = hn;
            g_inp[i] = hn;
            g_seq[((size_t)b*TT + t)*HH + j] = hn;
        }
        gsync();
    }
}

// ------------------------- Final: res = seq @ W_proj + b_proj, stored [B][V][T] -------------------------
#define FMA2(acc, av, wv) asm("fma.rn.f32x2 %0, %1, %2, %0;" : "+l"(acc) : "l"(av), "l"(wv))

__global__ void __launch_bounds__(256, 2)
k_sf(const float* __restrict__ Wp, const float* __restrict__ bp, float* __restrict__ out){
    __shared__ __align__(16) float sm[4224];    // As[16][132] | Bs[16][132] ; reused as sbuf[32][129]
    float* As = sm;
    float* Bs = sm + 2112;
    int m0 = blockIdx.x*128, n0 = blockIdx.y*128;
    int tid = threadIdx.x, tx = tid & 15, ty = tid >> 4;
    ull acc2[8][4];
    #pragma unroll
    for (int i=0;i<8;i++)
        #pragma unroll
        for (int j=0;j<4;j++) acc2[i][j] = 0ULL;

    for (int kc = 0; kc < HH; kc += 16){
        __syncthreads();
        #pragma unroll
        for (int i = 0; i < 8; i++){
            int idx = tid + i*256;        // 2048 = 128 m * 16 k
            int kk = idx & 15, m = idx >> 4;
            int r = m0 + m;
            As[kk*132 + m] = (r < BB*TT) ? g_seq[(size_t)r*HH + kc + kk] : 0.f;
        }
        #pragma unroll
        for (int i = 0; i < 8; i++){
            int idx = tid + i*256;        // 2048 = 16 k * 128 n
            int n = idx & 127, kk = idx >> 7;
            int v = n0 + n;
            Bs[kk*132 + n] = (v < VV) ? Wp[(size_t)(kc+kk)*VV + v] : 0.f;
        }
        __syncthreads();
        #pragma unroll 4
        for (int kk = 0; kk < 16; kk++){
            ull a2[8], w2[4];
            #pragma unroll
            for (int i = 0; i < 8; i++){
                float av = As[kk*132 + ty*8 + i];
                asm("mov.b64 %0, {%1, %2};" : "=l"(a2[i]) : "f"(av), "f"(av));
            }
            #pragma unroll
            for (int j = 0; j < 4; j++)
                w2[j] = *(const ull*)&Bs[kk*132 + tx*8 + 2*j];
            #pragma unroll
            for (int i = 0; i < 8; i++)
                #pragma unroll
                for (int j = 0; j < 4; j++)
                    FMA2(acc2[i][j], a2[i], w2[j]);
        }
    }
    // unpack
    float acc[8][8];
    #pragma unroll
    for (int i = 0; i < 8; i++)
        #pragma unroll
        for (int j = 0; j < 4; j++)
            asm("mov.b64 {%0, %1}, %2;" : "=f"(acc[i][2*j]), "=f"(acc[i][2*j+1]) : "l"(acc2[i][j]));
    // bias
    #pragma unroll
    for (int j = 0; j < 8; j++){
        int v = n0 + tx*8 + j;
        float bj = (v < VV) ? bp[v] : 0.f;
        #pragma unroll
        for (int i = 0; i < 8; i++) acc[i][j] += bj;
    }
    // transposed store via smem (32 output columns per pass)
    float* sbuf = sm;                     // [32][129]
    int lane = tid & 31, cbase = tid >> 5;
    for (int cg = 0; cg < 4; cg++){
        __syncthreads();
        if ((tx >> 2) == cg){
            #pragma unroll
            for (int j = 0; j < 8; j++){
                int cl = (tx & 3)*8 + j;
                #pragma unroll
                for (int i = 0; i < 8; i++)
                    sbuf[cl*129 + ty*8 + i] = acc[i][j];
            }
        }
        __syncthreads();
        #pragma unroll
        for (int cc = 0; cc < 4; cc++){
            int cl = cbase + cc*8;        // 0..31
            int v = n0 + cg*32 + cl;
            if (v < VV){
                #pragma unroll
                for (int q = 0; q < 4; q++){
                    int m = lane + q*32;
                    int r = m0 + m;
                    if (r < BB*TT){
                        int b = r / TT;
                        int t = r - b*TT;
                        out[(size_t)b*VV*TT + (size_t)v*TT + t] = sbuf[cl*129 + m];
                    }
                }
            }
        }
    }
}

// ------------------------- Argmax over V (tokens), t-coalesced -------------------------
__global__ void k_ag(float* __restrict__ out, int write_tok){
    int b = blockIdx.x;
    int t = threadIdx.x;
    if (t >= TT) return;
    const float* base = out + (size_t)b*VV*TT + t;
    float best = base[0];
    int bi = 0;
    #pragma unroll 4
    for (int v = 1; v < VV; v++){
        float x = base[(size_t)v*TT];
        if (x > best){ best = x; bi = v; }
    }
    if (write_tok)
        out[(size_t)BB*VV*TT + (size_t)b*TT + t] = (float)bi;
}

// ------------------------- launch -------------------------
extern "C" void kernel_launch(void* const* d_in, const int* in_sizes, int n_in,
                              void* d_out, int out_size){
    const float* enc_feat = (const float*)d_in[0];
    const float* W_fp   = (const float*)d_in[1];
    const float* b_fp   = (const float*)d_in[2];
    const float* W_enc  = (const float*)d_in[3];
    const float* b_enc  = (const float*)d_in[4];
    const float* W_dec  = (const float*)d_in[5];
    const float* b_dec  = (const float*)d_in[6];
    const float* W_full = (const float*)d_in[7];
    const float* b_full = (const float*)d_in[8];
    const float* W_comb = (const float*)d_in[9];
    const float* b_comb = (const float*)d_in[10];
    const float* embed  = (const float*)d_in[11];
    const float* W_ih   = (const float*)d_in[12];
    const float* b_ih   = (const float*)d_in[13];
    const float* W_hh   = (const float*)d_in[14];
    const float* b_hh   = (const float*)d_in[15];
    const float* W_proj = (const float*)d_in[16];
    const float* b_proj = (const float*)d_in[17];
    const int* start    = (n_in >= 19) ? (const int*)d_in[18] : nullptr;
    float* out = (float*)d_out;

    k_rst<<<1, 1>>>();
    k_p0<<<BB, 256>>>(embed, start);
    k_p1<<<dim3(2, BB), 256>>>(enc_feat, W_fp, b_fp);
    k_p2<<<BB, 256>>>(W_enc, b_enc);

    k_step<<<NBLK, 256>>>(W_dec, b_dec, W_full, b_full, W_comb, b_comb,
                          W_ih, b_ih, W_hh, b_hh);

    k_sf<<<dim3(76, 79), 256>>>(W_proj, b_proj, out);

    int write_tok = (out_size >= BB*VV*TT + BB*TT) ? 1 : 0;
    k_ag<<<BB, 192>>>(out, write_tok);
}